// round 14
// baseline (speedup 1.0000x reference)
#include <cuda_runtime.h>
#include <cuda_bf16.h>
#include <cuda_fp16.h>
#include <cstdint>
#include <math.h>

#define SEQ 8192
#define DIM 1024
#define NCH 4                      // row chunks for QK->softmax->PV pipelining
#define CHROWS (SEQ / NCH)         // 2048

// ---------------------------------------------------------------------------
// Scratch (device globals — allocation-free)
// ---------------------------------------------------------------------------
__device__ __align__(256) float g_S[(size_t)SEQ * SEQ];     // 256MB logits
__device__ __align__(256) __half g_Ph[(size_t)SEQ * SEQ];   // 128MB probs (fp16)
__device__ __align__(256) __half g_Qh[SEQ * DIM], g_Qm[SEQ * DIM];
__device__ __align__(256) __half g_Kh[SEQ * DIM], g_Km[SEQ * DIM];
__device__ __align__(256) __half g_Xh[SEQ * DIM], g_Xm[SEQ * DIM];
__device__ __align__(256) __half g_Xth[DIM * SEQ];
__device__ __align__(256) __half g_Wqh[DIM * DIM], g_Wqm[DIM * DIM];
__device__ __align__(256) __half g_Wkh[DIM * DIM], g_Wkm[DIM * DIM];

// ---------------------------------------------------------------------------
// PTX helpers (baseline ISA only — valid on .target sm_103)
// ---------------------------------------------------------------------------
__device__ __forceinline__ uint32_t smem_u32(const void* p) {
    uint32_t a;
    asm("{ .reg .u64 t; cvta.to.shared.u64 t, %1; cvt.u32.u64 %0, t; }"
        : "=r"(a) : "l"(p));
    return a;
}

__device__ __forceinline__ void cp_async16(uint32_t saddr, const void* gaddr) {
    asm volatile("cp.async.cg.shared.global [%0], [%1], 16;"
                 :: "r"(saddr), "l"(gaddr));
}
#define CP_COMMIT() asm volatile("cp.async.commit_group;")
#define CP_WAIT(N)  asm volatile("cp.async.wait_group %0;" :: "n"(N))

__device__ __forceinline__ void ldsm4(uint32_t* r, uint32_t addr) {
    asm volatile("ldmatrix.sync.aligned.m8n8.x4.shared.b16 {%0,%1,%2,%3}, [%4];"
                 : "=r"(r[0]), "=r"(r[1]), "=r"(r[2]), "=r"(r[3])
                 : "r"(addr));
}

// fp16 inputs, fp32 accumulate
__device__ __forceinline__ void mma16816(float* d, const uint32_t* a,
                                         uint32_t b0, uint32_t b1) {
    asm volatile(
        "mma.sync.aligned.m16n8k16.row.col.f32.f16.f16.f32 "
        "{%0,%1,%2,%3}, {%4,%5,%6,%7}, {%8,%9}, {%0,%1,%2,%3};"
        : "+f"(d[0]), "+f"(d[1]), "+f"(d[2]), "+f"(d[3])
        : "r"(a[0]), "r"(a[1]), "r"(a[2]), "r"(a[3]), "r"(b0), "r"(b1));
}

// swizzled smem byte offset for (row, 16B-segment 0..3) in a 64B-pitch tile
__device__ __forceinline__ uint32_t swz64(int row, int seg) {
    return (uint32_t)(row * 64 + ((seg ^ ((row >> 1) & 3)) << 4));
}

// ---------------------------------------------------------------------------
// Multi-plane HMMA GEMM, all products accumulated into ONE output:
//   MODE 0:  D = alpha * (A0@B0^T + A0@B1^T + A1@B0^T)    (3-product split)
//   MODE 1:  D = alpha * (A0@B0^T)                        (plain GEMM)
// CTA: 128 threads (2x2 warps, warp tile 64x64), tile 128x128, BK=32.
// moff = row offset (row-chunked launches). 2 CTAs/SM.
// EPI 0: C = alpha*D (fp32, streaming store). EPI 1: 2-way fp16 split of D.
// ---------------------------------------------------------------------------
struct GemmArgs {
    const void* A[2];
    const void* B[2];
    const void* B2[2];
    int K;        // reduction length (multiple of 32)
    int ldc;
    int moff;     // output/input row offset
    float alpha;
    float* C;
    __half *Oh, *Om, *Oh2, *Om2;
};

template <int MODE, int EPI>
__global__ __launch_bounds__(128, 2)
void gemm_mma(const GemmArgs args)
{
    constexpr int BM = 128, BN = 128, BK = 32;
    constexpr int NA = (MODE == 0) ? 2 : 1;
    constexpr int NB = (MODE == 0) ? 2 : 1;
    constexpr int STAGES = (MODE == 0) ? 3 : 6;
    constexpr int A_PL = BM * 64;                  // 8KB per A plane
    constexpr int B_PL = BN * 64;                  // 8KB per B plane
    constexpr int STAGE_B = NA * A_PL + NB * B_PL; // 32KB / 16KB
    extern __shared__ __align__(128) char smem[];
    const uint32_t sbase = smem_u32(smem);

    const int tid = threadIdx.x;
    const int wid = tid >> 5;
    const int lane = tid & 31;
    const int wm = wid & 1;          // 2 warps along M (64 rows each)
    const int wn = wid >> 1;         // 2 warps along N (64 cols each)
    const int bm = args.moff + blockIdx.y * BM;
    const int bn = blockIdx.x * BN;
    const int K = args.K;
    const int nchunk = K / BK;
    const int z = blockIdx.z;
    const void* const* Bset = z ? args.B2 : args.B;

    // per-lane ldmatrix offsets: 2 k16-steps per BK=32 chunk
    const int sub = lane >> 3, r8 = lane & 7;
    uint32_t aoff[2][4], boff[2][4];
#pragma unroll
    for (int kk = 0; kk < 2; kk++) {
#pragma unroll
        for (int mi = 0; mi < 4; mi++) {
            int row = wm * 64 + mi * 16 + (sub & 1) * 8 + r8;
            int seg = 2 * kk + (sub >> 1);
            aoff[kk][mi] = swz64(row, seg);
        }
#pragma unroll
        for (int nj = 0; nj < 4; nj++) {
            int row = wn * 64 + nj * 16 + (sub >> 1) * 8 + r8;
            int seg = 2 * kk + (sub & 1);
            boff[kk][nj] = swz64(row, seg);
        }
    }

    // cp.async mapping: 32 rows x 4 segs per pass (128 threads)
    const int ld_row = tid >> 2;         // 0..31
    const int ld_seg = tid & 3;          // 0..3
    const size_t g_off0 = (size_t)ld_row * K + ld_seg * 8;

    float acc[4][8][4];
#pragma unroll
    for (int mi = 0; mi < 4; mi++)
#pragma unroll
        for (int ni = 0; ni < 8; ni++)
#pragma unroll
            for (int v = 0; v < 4; v++) acc[mi][ni][v] = 0.0f;

    auto issue_tile = [&](int c, int s) {
        const uint32_t sb = sbase + s * STAGE_B;
        const size_t rstep = (size_t)32 * K;
#pragma unroll
        for (int pl = 0; pl < NA; pl++) {
            const unsigned short* Ap =
                (const unsigned short*)args.A[pl] + (size_t)bm * K + c * BK;
            const uint32_t abase = sb + pl * A_PL;
#pragma unroll
            for (int r = 0; r < 4; r++)
                cp_async16(abase + swz64(ld_row + r * 32, ld_seg),
                           Ap + g_off0 + r * rstep);
        }
#pragma unroll
        for (int pl = 0; pl < NB; pl++) {
            const unsigned short* Bp =
                (const unsigned short*)Bset[pl] + (size_t)bn * K + c * BK;
            const uint32_t bbase = sb + NA * A_PL + pl * B_PL;
#pragma unroll
            for (int r = 0; r < 4; r++)
                cp_async16(bbase + swz64(ld_row + r * 32, ld_seg),
                           Bp + g_off0 + r * rstep);
        }
    };

    // prologue: stages 0..STAGES-2 in flight
#pragma unroll
    for (int j = 0; j < STAGES - 1; j++) {
        issue_tile(j, j);
        CP_COMMIT();
    }
    CP_WAIT(STAGES - 2);
    __syncthreads();

    for (int i = 0; i < nchunk; i++) {
        if (i + STAGES - 1 < nchunk) {
            issue_tile(i + STAGES - 1, (i + STAGES - 1) % STAGES);
            CP_COMMIT();
        }

        const uint32_t sb = sbase + (i % STAGES) * STAGE_B;
        const uint32_t a0 = sb, a1 = sb + A_PL;
        const uint32_t b0 = sb + NA * A_PL, b1 = b0 + B_PL;
#pragma unroll
        for (int kk = 0; kk < 2; kk++) {
            uint32_t bh[4][4];
#pragma unroll
            for (int nj = 0; nj < 4; nj++) ldsm4(bh[nj], b0 + boff[kk][nj]);
            uint32_t bm_[4][4];
            if (MODE == 0) {
#pragma unroll
                for (int nj = 0; nj < 4; nj++) ldsm4(bm_[nj], b1 + boff[kk][nj]);
            }
#pragma unroll
            for (int mi = 0; mi < 4; mi++) {
                uint32_t ah[4];
                ldsm4(ah, a0 + aoff[kk][mi]);
#pragma unroll
                for (int ni = 0; ni < 8; ni++) {
                    const int nj = ni >> 1, o = (ni & 1) * 2;
                    mma16816(acc[mi][ni], ah, bh[nj][o], bh[nj][o + 1]);
                }
                if (MODE == 0) {
                    uint32_t am[4];
                    ldsm4(am, a1 + aoff[kk][mi]);
#pragma unroll
                    for (int ni = 0; ni < 8; ni++) {
                        const int nj = ni >> 1, o = (ni & 1) * 2;
                        mma16816(acc[mi][ni], ah, bm_[nj][o], bm_[nj][o + 1]);
                    }
#pragma unroll
                    for (int ni = 0; ni < 8; ni++) {
                        const int nj = ni >> 1, o = (ni & 1) * 2;
                        mma16816(acc[mi][ni], am, bh[nj][o], bh[nj][o + 1]);
                    }
                }
            }
        }
        CP_WAIT(STAGES - 2);
        __syncthreads();
    }

    // ---- epilogue from registers ----
    const int ldc = args.ldc;
    __half* Ohp = z ? args.Oh2 : args.Oh;
    __half* Omp = z ? args.Om2 : args.Om;
#pragma unroll
    for (int mi = 0; mi < 4; mi++) {
#pragma unroll
        for (int ni = 0; ni < 8; ni++) {
            const int r0 = bm + wm * 64 + mi * 16 + (lane >> 2);
            const int c0 = bn + wn * 64 + ni * 8 + (lane & 3) * 2;
#pragma unroll
            for (int h = 0; h < 2; h++) {
                const size_t o = (size_t)(r0 + h * 8) * ldc + c0;
                const float v0 = acc[mi][ni][2 * h + 0];
                const float v1 = acc[mi][ni][2 * h + 1];
                if (EPI == 0) {
                    float2 w;
                    w.x = args.alpha * v0;
                    w.y = args.alpha * v1;
                    __stcs((float2*)(args.C + o), w);
                } else {
                    __half h0 = __float2half_rn(v0);
                    __half h1 = __float2half_rn(v1);
                    __half m0 = __float2half_rn(v0 - __half2float(h0));
                    __half m1 = __float2half_rn(v1 - __half2float(h1));
                    uint32_t ph = (uint32_t)*(unsigned short*)&h0 |
                                  ((uint32_t)*(unsigned short*)&h1 << 16);
                    uint32_t pm = (uint32_t)*(unsigned short*)&m0 |
                                  ((uint32_t)*(unsigned short*)&m1 << 16);
                    *(uint32_t*)((unsigned short*)Ohp + o) = ph;
                    *(uint32_t*)((unsigned short*)Omp + o) = pm;
                }
            }
        }
    }
}

// ---------------------------------------------------------------------------
// prep_x: one read of X -> Xh, Xm (row-major fp16 split) + Xth (fp16 transpose)
// ---------------------------------------------------------------------------
__global__ __launch_bounds__(256)
void prep_x(const float* __restrict__ X, __half* __restrict__ Xh,
            __half* __restrict__ Xm, __half* __restrict__ Xth)
{
    __shared__ float t[32][33];
    const int bc = blockIdx.x * 32, br = blockIdx.y * 32;
    const int tx = threadIdx.x & 31, ty = threadIdx.x >> 5;
#pragma unroll
    for (int j = 0; j < 32; j += 8) {
        size_t idx = (size_t)(br + ty + j) * DIM + bc + tx;
        float v = X[idx];
        t[ty + j][tx] = v;
        __half h = __float2half_rn(v);
        Xh[idx] = h;
        Xm[idx] = __float2half_rn(v - __half2float(h));
    }
    __syncthreads();
#pragma unroll
    for (int j = 0; j < 32; j += 8) {
        int oc = bc + ty + j;
        Xth[(size_t)oc * SEQ + br + tx] = __float2half_rn(t[tx][ty + j]);
    }
}

// ---------------------------------------------------------------------------
// transpose + 2-way fp16 split: in[R][C] fp32 -> oh/om [C][R] fp16
// blockIdx.z selects (input, output) pair — merged Wq/Wk transpose.
// ---------------------------------------------------------------------------
__global__ __launch_bounds__(256)
void transp_split2h_dual(const float* __restrict__ in0, __half* oh0, __half* om0,
                         const float* __restrict__ in1, __half* oh1, __half* om1,
                         int R, int C)
{
    const float* in = blockIdx.z ? in1 : in0;
    __half* oh = blockIdx.z ? oh1 : oh0;
    __half* om = blockIdx.z ? om1 : om0;
    __shared__ float t[32][33];
    const int bc = blockIdx.x * 32, br = blockIdx.y * 32;
    const int tx = threadIdx.x & 31, ty = threadIdx.x >> 5;
#pragma unroll
    for (int j = 0; j < 32; j += 8)
        t[ty + j][tx] = in[(size_t)(br + ty + j) * C + bc + tx];
    __syncthreads();
#pragma unroll
    for (int j = 0; j < 32; j += 8) {
        int oc = bc + ty + j;
        float v = t[tx][ty + j];
        __half h = __float2half_rn(v);
        size_t o = (size_t)oc * R + br + tx;
        oh[o] = h;
        om[o] = __float2half_rn(v - __half2float(h));
    }
}

// ---------------------------------------------------------------------------
// softmax over rows [row0, row0+grid) of S, emitting fp16 P.
// ---------------------------------------------------------------------------
__global__ __launch_bounds__(512)
void softmax_h(const float* __restrict__ S, __half* __restrict__ Ph,
               int n, int row0)
{
    __shared__ float row[SEQ];
    __shared__ float red[16];
    const int tid = threadIdx.x;
    const int lane = tid & 31;
    const int warp = tid >> 5;
    const int r = row0 + blockIdx.x;
    const int nv = n / 4;
    const float4* s4 = (const float4*)(S + (size_t)r * n);
    float4* r4 = (float4*)row;

    float m = -3.4e38f;
    for (int i = tid; i < nv; i += 512) {
        float4 v = __ldcs(s4 + i);
        r4[i] = v;
        m = fmaxf(fmaxf(m, v.x), fmaxf(v.y, fmaxf(v.z, v.w)));
    }
#pragma unroll
    for (int o = 16; o > 0; o >>= 1)
        m = fmaxf(m, __shfl_xor_sync(0xffffffffu, m, o));
    if (lane == 0) red[warp] = m;
    __syncthreads();
    {
        float t = red[lane & 15];
#pragma unroll
        for (int o = 8; o > 0; o >>= 1)
            t = fmaxf(t, __shfl_xor_sync(0xffffffffu, t, o));
        m = __shfl_sync(0xffffffffu, t, 0);
    }
    __syncthreads();

    float sum = 0.0f;
    for (int i = tid; i < nv; i += 512) {
        float4 v = r4[i];
        v.x = __expf(v.x - m);
        v.y = __expf(v.y - m);
        v.z = __expf(v.z - m);
        v.w = __expf(v.w - m);
        r4[i] = v;
        sum += v.x + v.y + v.z + v.w;
    }
#pragma unroll
    for (int o = 16; o > 0; o >>= 1)
        sum += __shfl_xor_sync(0xffffffffu, sum, o);
    if (lane == 0) red[warp] = sum;
    __syncthreads();
    {
        float t = red[lane & 15];
#pragma unroll
        for (int o = 8; o > 0; o >>= 1)
            t += __shfl_xor_sync(0xffffffffu, t, o);
        sum = __shfl_sync(0xffffffffu, t, 0);
    }
    const float inv = 1.0f / sum;
    __syncthreads();

    unsigned short* ph = (unsigned short*)(Ph + (size_t)r * n);
    for (int i = tid; i < nv; i += 512) {
        float4 v = r4[i];
        __half h0 = __float2half_rn(v.x * inv);
        __half h1 = __float2half_rn(v.y * inv);
        __half h2 = __float2half_rn(v.z * inv);
        __half h3 = __float2half_rn(v.w * inv);
        int2 wh;
        wh.x = (int)((uint32_t)*(unsigned short*)&h0 |
                     ((uint32_t)*(unsigned short*)&h1 << 16));
        wh.y = (int)((uint32_t)*(unsigned short*)&h2 |
                     ((uint32_t)*(unsigned short*)&h3 << 16));
        __stcs((int2*)(ph + i * 4), wh);
    }
}

// ---------------------------------------------------------------------------
extern "C" void kernel_launch(void* const* d_in, const int* in_sizes, int n_in,
                              void* d_out, int out_size)
{
    const float* X  = (const float*)d_in[0];
    const float* Wq = (const float*)d_in[1];
    const float* Wk = (const float*)d_in[2];
    float* out = (float*)d_out;

    void* p;
#define SYM(name, var) cudaGetSymbolAddress(&p, name); auto* var = (decltype(&name[0]))p;
    SYM(g_S, S) SYM(g_Ph, Ph)
    SYM(g_Qh, Qh) SYM(g_Qm, Qm)
    SYM(g_Kh, Kh) SYM(g_Km, Km)
    SYM(g_Xh, Xh) SYM(g_Xm, Xm)
    SYM(g_Xth, Xth)
    SYM(g_Wqh, Wqh) SYM(g_Wqm, Wqm)
    SYM(g_Wkh, Wkh) SYM(g_Wkm, Wkm)
#undef SYM

    const int SMEM_M0 = 3 * 32768;   // 3 stages x 32KB (2 CTAs/SM)
    const int SMEM_M1 = 6 * 16384;   // 6 stages x 16KB (2 CTAs/SM)
    cudaFuncSetAttribute(gemm_mma<0, 1>, cudaFuncAttributeMaxDynamicSharedMemorySize, SMEM_M0);
    cudaFuncSetAttribute(gemm_mma<0, 0>, cudaFuncAttributeMaxDynamicSharedMemorySize, SMEM_M0);
    cudaFuncSetAttribute(gemm_mma<1, 0>, cudaFuncAttributeMaxDynamicSharedMemorySize, SMEM_M1);

    // side stream + events for the QK->softmax->PV row-chunk pipeline
    cudaStream_t s1;
    cudaStreamCreateWithFlags(&s1, cudaStreamNonBlocking);
    cudaEvent_t evq[NCH], evd;
    for (int c = 0; c < NCH; c++)
        cudaEventCreateWithFlags(&evq[c], cudaEventDisableTiming);
    cudaEventCreateWithFlags(&evd, cudaEventDisableTiming);

    // --- prep (main stream) ---
    prep_x<<<dim3(DIM / 32, SEQ / 32), 256>>>(X, Xh, Xm, Xth);
    transp_split2h_dual<<<dim3(DIM / 32, DIM / 32, 2), 256>>>(
        Wq, Wqh, Wqm, Wk, Wkh, Wkm, DIM, DIM);

    // --- projections Q and K in one launch (z selects weight set) ---
    {
        GemmArgs a{};
        a.A[0] = Xh;  a.A[1] = Xm;
        a.B[0] = Wqh; a.B[1] = Wqm;
        a.B2[0] = Wkh; a.B2[1] = Wkm;
        a.K = DIM; a.ldc = DIM; a.moff = 0; a.alpha = 1.0f;
        a.Oh = Qh; a.Om = Qm; a.Oh2 = Kh; a.Om2 = Km;
        gemm_mma<0, 1><<<dim3(DIM / 128, SEQ / 128, 2), 128, SMEM_M0>>>(a);
    }

    // --- pipelined: QK chunk c (main) ; softmax_c + PV_c (s1) ---
    for (int c = 0; c < NCH; c++) {
        // S[rows c] = (Q @ K^T)/32 for this row chunk
        {
            GemmArgs a{};
            a.A[0] = Qh; a.A[1] = Qm;
            a.B[0] = Kh; a.B[1] = Km;
            a.K = DIM; a.ldc = SEQ; a.moff = c * CHROWS; a.alpha = 0.03125f;
            a.C = S;
            gemm_mma<0, 0><<<dim3(SEQ / 128, CHROWS / 128, 1), 128, SMEM_M0>>>(a);
        }
        cudaEventRecord(evq[c], 0);
        cudaStreamWaitEvent(s1, evq[c], 0);
        softmax_h<<<CHROWS, 512, 0, s1>>>(S, Ph, SEQ, c * CHROWS);
        {
            GemmArgs a{};
            a.A[0] = Ph;
            a.B[0] = Xth;
            a.K = SEQ; a.ldc = DIM; a.moff = c * CHROWS; a.alpha = 1.0f;
            a.C = out;
            gemm_mma<1, 0><<<dim3(DIM / 128, CHROWS / 128, 1), 128, SMEM_M1, s1>>>(a);
        }
    }

    // join side stream back into the main stream
    cudaEventRecord(evd, s1);
    cudaStreamWaitEvent(0, evd, 0);

    for (int c = 0; c < NCH; c++) cudaEventDestroy(evq[c]);
    cudaEventDestroy(evd);
    cudaStreamDestroy(s1);
}

// round 15
// speedup vs baseline: 1.0448x; 1.0448x over previous
#include <cuda_runtime.h>
#include <cuda_bf16.h>
#include <cuda_fp16.h>
#include <cstdint>
#include <math.h>

#define SEQ 8192
#define DIM 1024
#define NCH 2                      // row chunks for QK->softmax->PV pipelining
#define CHROWS (SEQ / NCH)         // 4096

// ---------------------------------------------------------------------------
// Scratch (device globals — allocation-free)
// ---------------------------------------------------------------------------
__device__ __align__(256) float g_S[(size_t)SEQ * SEQ];     // 256MB logits
__device__ __align__(256) __half g_Ph[(size_t)SEQ * SEQ];   // 128MB probs (fp16)
__device__ __align__(256) __half g_Qh[SEQ * DIM], g_Qm[SEQ * DIM];
__device__ __align__(256) __half g_Kh[SEQ * DIM], g_Km[SEQ * DIM];
__device__ __align__(256) __half g_Xh[SEQ * DIM], g_Xm[SEQ * DIM];
__device__ __align__(256) __half g_Xth[DIM * SEQ];
__device__ __align__(256) __half g_Wqh[DIM * DIM], g_Wqm[DIM * DIM];
__device__ __align__(256) __half g_Wkh[DIM * DIM], g_Wkm[DIM * DIM];

// ---------------------------------------------------------------------------
// PTX helpers (baseline ISA only — valid on .target sm_103)
// ---------------------------------------------------------------------------
__device__ __forceinline__ uint32_t smem_u32(const void* p) {
    uint32_t a;
    asm("{ .reg .u64 t; cvta.to.shared.u64 t, %1; cvt.u32.u64 %0, t; }"
        : "=r"(a) : "l"(p));
    return a;
}

__device__ __forceinline__ void cp_async16(uint32_t saddr, const void* gaddr) {
    asm volatile("cp.async.cg.shared.global [%0], [%1], 16;"
                 :: "r"(saddr), "l"(gaddr));
}
#define CP_COMMIT() asm volatile("cp.async.commit_group;")
#define CP_WAIT(N)  asm volatile("cp.async.wait_group %0;" :: "n"(N))

__device__ __forceinline__ void ldsm4(uint32_t* r, uint32_t addr) {
    asm volatile("ldmatrix.sync.aligned.m8n8.x4.shared.b16 {%0,%1,%2,%3}, [%4];"
                 : "=r"(r[0]), "=r"(r[1]), "=r"(r[2]), "=r"(r[3])
                 : "r"(addr));
}

// fp16 inputs, fp32 accumulate
__device__ __forceinline__ void mma16816(float* d, const uint32_t* a,
                                         uint32_t b0, uint32_t b1) {
    asm volatile(
        "mma.sync.aligned.m16n8k16.row.col.f32.f16.f16.f32 "
        "{%0,%1,%2,%3}, {%4,%5,%6,%7}, {%8,%9}, {%0,%1,%2,%3};"
        : "+f"(d[0]), "+f"(d[1]), "+f"(d[2]), "+f"(d[3])
        : "r"(a[0]), "r"(a[1]), "r"(a[2]), "r"(a[3]), "r"(b0), "r"(b1));
}

// swizzled smem byte offset for (row, 16B-segment 0..3) in a 64B-pitch tile
__device__ __forceinline__ uint32_t swz64(int row, int seg) {
    return (uint32_t)(row * 64 + ((seg ^ ((row >> 1) & 3)) << 4));
}

// ---------------------------------------------------------------------------
// Multi-plane HMMA GEMM, all products accumulated into ONE output:
//   MODE 0:  D = alpha * (A0@B0^T + A0@B1^T + A1@B0^T)    (3-product split)
//   MODE 1:  D = alpha * (A0@B0^T)                        (plain GEMM)
// CTA: 128 threads (2x2 warps, warp tile 64x64), tile 128x128, BK=32.
// moff = row offset (row-chunked launches). 2 CTAs/SM.
// EPI 0: C = alpha*D (fp32, streaming store). EPI 1: 2-way fp16 split of D.
// ---------------------------------------------------------------------------
struct GemmArgs {
    const void* A[2];
    const void* B[2];
    const void* B2[2];
    int K;        // reduction length (multiple of 32)
    int ldc;
    int moff;     // output/input row offset
    float alpha;
    float* C;
    __half *Oh, *Om, *Oh2, *Om2;
};

template <int MODE, int EPI>
__global__ __launch_bounds__(128, 2)
void gemm_mma(const GemmArgs args)
{
    constexpr int BM = 128, BN = 128, BK = 32;
    constexpr int NA = (MODE == 0) ? 2 : 1;
    constexpr int NB = (MODE == 0) ? 2 : 1;
    constexpr int STAGES = (MODE == 0) ? 3 : 6;
    constexpr int A_PL = BM * 64;                  // 8KB per A plane
    constexpr int B_PL = BN * 64;                  // 8KB per B plane
    constexpr int STAGE_B = NA * A_PL + NB * B_PL; // 32KB / 16KB
    extern __shared__ __align__(128) char smem[];
    const uint32_t sbase = smem_u32(smem);

    const int tid = threadIdx.x;
    const int wid = tid >> 5;
    const int lane = tid & 31;
    const int wm = wid & 1;          // 2 warps along M (64 rows each)
    const int wn = wid >> 1;         // 2 warps along N (64 cols each)
    const int bm = args.moff + blockIdx.y * BM;
    const int bn = blockIdx.x * BN;
    const int K = args.K;
    const int nchunk = K / BK;
    const int z = blockIdx.z;
    const void* const* Bset = z ? args.B2 : args.B;

    // per-lane ldmatrix offsets: 2 k16-steps per BK=32 chunk
    const int sub = lane >> 3, r8 = lane & 7;
    uint32_t aoff[2][4], boff[2][4];
#pragma unroll
    for (int kk = 0; kk < 2; kk++) {
#pragma unroll
        for (int mi = 0; mi < 4; mi++) {
            int row = wm * 64 + mi * 16 + (sub & 1) * 8 + r8;
            int seg = 2 * kk + (sub >> 1);
            aoff[kk][mi] = swz64(row, seg);
        }
#pragma unroll
        for (int nj = 0; nj < 4; nj++) {
            int row = wn * 64 + nj * 16 + (sub >> 1) * 8 + r8;
            int seg = 2 * kk + (sub & 1);
            boff[kk][nj] = swz64(row, seg);
        }
    }

    // cp.async mapping: 32 rows x 4 segs per pass (128 threads)
    const int ld_row = tid >> 2;         // 0..31
    const int ld_seg = tid & 3;          // 0..3
    const size_t g_off0 = (size_t)ld_row * K + ld_seg * 8;

    float acc[4][8][4];
#pragma unroll
    for (int mi = 0; mi < 4; mi++)
#pragma unroll
        for (int ni = 0; ni < 8; ni++)
#pragma unroll
            for (int v = 0; v < 4; v++) acc[mi][ni][v] = 0.0f;

    auto issue_tile = [&](int c, int s) {
        const uint32_t sb = sbase + s * STAGE_B;
        const size_t rstep = (size_t)32 * K;
#pragma unroll
        for (int pl = 0; pl < NA; pl++) {
            const unsigned short* Ap =
                (const unsigned short*)args.A[pl] + (size_t)bm * K + c * BK;
            const uint32_t abase = sb + pl * A_PL;
#pragma unroll
            for (int r = 0; r < 4; r++)
                cp_async16(abase + swz64(ld_row + r * 32, ld_seg),
                           Ap + g_off0 + r * rstep);
        }
#pragma unroll
        for (int pl = 0; pl < NB; pl++) {
            const unsigned short* Bp =
                (const unsigned short*)Bset[pl] + (size_t)bn * K + c * BK;
            const uint32_t bbase = sb + NA * A_PL + pl * B_PL;
#pragma unroll
            for (int r = 0; r < 4; r++)
                cp_async16(bbase + swz64(ld_row + r * 32, ld_seg),
                           Bp + g_off0 + r * rstep);
        }
    };

    // prologue: stages 0..STAGES-2 in flight
#pragma unroll
    for (int j = 0; j < STAGES - 1; j++) {
        issue_tile(j, j);
        CP_COMMIT();
    }
    CP_WAIT(STAGES - 2);
    __syncthreads();

    for (int i = 0; i < nchunk; i++) {
        if (i + STAGES - 1 < nchunk) {
            issue_tile(i + STAGES - 1, (i + STAGES - 1) % STAGES);
            CP_COMMIT();
        }

        const uint32_t sb = sbase + (i % STAGES) * STAGE_B;
        const uint32_t a0 = sb, a1 = sb + A_PL;
        const uint32_t b0 = sb + NA * A_PL, b1 = b0 + B_PL;
#pragma unroll
        for (int kk = 0; kk < 2; kk++) {
            uint32_t bh[4][4];
#pragma unroll
            for (int nj = 0; nj < 4; nj++) ldsm4(bh[nj], b0 + boff[kk][nj]);
            uint32_t bm_[4][4];
            if (MODE == 0) {
#pragma unroll
                for (int nj = 0; nj < 4; nj++) ldsm4(bm_[nj], b1 + boff[kk][nj]);
            }
#pragma unroll
            for (int mi = 0; mi < 4; mi++) {
                uint32_t ah[4];
                ldsm4(ah, a0 + aoff[kk][mi]);
#pragma unroll
                for (int ni = 0; ni < 8; ni++) {
                    const int nj = ni >> 1, o = (ni & 1) * 2;
                    mma16816(acc[mi][ni], ah, bh[nj][o], bh[nj][o + 1]);
                }
                if (MODE == 0) {
                    uint32_t am[4];
                    ldsm4(am, a1 + aoff[kk][mi]);
#pragma unroll
                    for (int ni = 0; ni < 8; ni++) {
                        const int nj = ni >> 1, o = (ni & 1) * 2;
                        mma16816(acc[mi][ni], ah, bm_[nj][o], bm_[nj][o + 1]);
                    }
#pragma unroll
                    for (int ni = 0; ni < 8; ni++) {
                        const int nj = ni >> 1, o = (ni & 1) * 2;
                        mma16816(acc[mi][ni], am, bh[nj][o], bh[nj][o + 1]);
                    }
                }
            }
        }
        CP_WAIT(STAGES - 2);
        __syncthreads();
    }

    // ---- epilogue from registers ----
    const int ldc = args.ldc;
    __half* Ohp = z ? args.Oh2 : args.Oh;
    __half* Omp = z ? args.Om2 : args.Om;
#pragma unroll
    for (int mi = 0; mi < 4; mi++) {
#pragma unroll
        for (int ni = 0; ni < 8; ni++) {
            const int r0 = bm + wm * 64 + mi * 16 + (lane >> 2);
            const int c0 = bn + wn * 64 + ni * 8 + (lane & 3) * 2;
#pragma unroll
            for (int h = 0; h < 2; h++) {
                const size_t o = (size_t)(r0 + h * 8) * ldc + c0;
                const float v0 = acc[mi][ni][2 * h + 0];
                const float v1 = acc[mi][ni][2 * h + 1];
                if (EPI == 0) {
                    float2 w;
                    w.x = args.alpha * v0;
                    w.y = args.alpha * v1;
                    __stcs((float2*)(args.C + o), w);
                } else {
                    __half h0 = __float2half_rn(v0);
                    __half h1 = __float2half_rn(v1);
                    __half m0 = __float2half_rn(v0 - __half2float(h0));
                    __half m1 = __float2half_rn(v1 - __half2float(h1));
                    uint32_t ph = (uint32_t)*(unsigned short*)&h0 |
                                  ((uint32_t)*(unsigned short*)&h1 << 16);
                    uint32_t pm = (uint32_t)*(unsigned short*)&m0 |
                                  ((uint32_t)*(unsigned short*)&m1 << 16);
                    *(uint32_t*)((unsigned short*)Ohp + o) = ph;
                    *(uint32_t*)((unsigned short*)Omp + o) = pm;
                }
            }
        }
    }
}

// ---------------------------------------------------------------------------
// prep_x: one read of X -> Xh, Xm (row-major fp16 split) + Xth (fp16 transpose)
// ---------------------------------------------------------------------------
__global__ __launch_bounds__(256)
void prep_x(const float* __restrict__ X, __half* __restrict__ Xh,
            __half* __restrict__ Xm, __half* __restrict__ Xth)
{
    __shared__ float t[32][33];
    const int bc = blockIdx.x * 32, br = blockIdx.y * 32;
    const int tx = threadIdx.x & 31, ty = threadIdx.x >> 5;
#pragma unroll
    for (int j = 0; j < 32; j += 8) {
        size_t idx = (size_t)(br + ty + j) * DIM + bc + tx;
        float v = X[idx];
        t[ty + j][tx] = v;
        __half h = __float2half_rn(v);
        Xh[idx] = h;
        Xm[idx] = __float2half_rn(v - __half2float(h));
    }
    __syncthreads();
#pragma unroll
    for (int j = 0; j < 32; j += 8) {
        int oc = bc + ty + j;
        Xth[(size_t)oc * SEQ + br + tx] = __float2half_rn(t[tx][ty + j]);
    }
}

// ---------------------------------------------------------------------------
// transpose + 2-way fp16 split: in[R][C] fp32 -> oh/om [C][R] fp16
// blockIdx.z selects (input, output) pair — merged Wq/Wk transpose.
// ---------------------------------------------------------------------------
__global__ __launch_bounds__(256)
void transp_split2h_dual(const float* __restrict__ in0, __half* oh0, __half* om0,
                         const float* __restrict__ in1, __half* oh1, __half* om1,
                         int R, int C)
{
    const float* in = blockIdx.z ? in1 : in0;
    __half* oh = blockIdx.z ? oh1 : oh0;
    __half* om = blockIdx.z ? om1 : om0;
    __shared__ float t[32][33];
    const int bc = blockIdx.x * 32, br = blockIdx.y * 32;
    const int tx = threadIdx.x & 31, ty = threadIdx.x >> 5;
#pragma unroll
    for (int j = 0; j < 32; j += 8)
        t[ty + j][tx] = in[(size_t)(br + ty + j) * C + bc + tx];
    __syncthreads();
#pragma unroll
    for (int j = 0; j < 32; j += 8) {
        int oc = bc + ty + j;
        float v = t[tx][ty + j];
        __half h = __float2half_rn(v);
        size_t o = (size_t)oc * R + br + tx;
        oh[o] = h;
        om[o] = __float2half_rn(v - __half2float(h));
    }
}

// ---------------------------------------------------------------------------
// softmax over rows [row0, row0+grid) of S, emitting fp16 P.
// ---------------------------------------------------------------------------
__global__ __launch_bounds__(512)
void softmax_h(const float* __restrict__ S, __half* __restrict__ Ph,
               int n, int row0)
{
    __shared__ float row[SEQ];
    __shared__ float red[16];
    const int tid = threadIdx.x;
    const int lane = tid & 31;
    const int warp = tid >> 5;
    const int r = row0 + blockIdx.x;
    const int nv = n / 4;
    const float4* s4 = (const float4*)(S + (size_t)r * n);
    float4* r4 = (float4*)row;

    float m = -3.4e38f;
    for (int i = tid; i < nv; i += 512) {
        float4 v = __ldcs(s4 + i);
        r4[i] = v;
        m = fmaxf(fmaxf(m, v.x), fmaxf(v.y, fmaxf(v.z, v.w)));
    }
#pragma unroll
    for (int o = 16; o > 0; o >>= 1)
        m = fmaxf(m, __shfl_xor_sync(0xffffffffu, m, o));
    if (lane == 0) red[warp] = m;
    __syncthreads();
    {
        float t = red[lane & 15];
#pragma unroll
        for (int o = 8; o > 0; o >>= 1)
            t = fmaxf(t, __shfl_xor_sync(0xffffffffu, t, o));
        m = __shfl_sync(0xffffffffu, t, 0);
    }
    __syncthreads();

    float sum = 0.0f;
    for (int i = tid; i < nv; i += 512) {
        float4 v = r4[i];
        v.x = __expf(v.x - m);
        v.y = __expf(v.y - m);
        v.z = __expf(v.z - m);
        v.w = __expf(v.w - m);
        r4[i] = v;
        sum += v.x + v.y + v.z + v.w;
    }
#pragma unroll
    for (int o = 16; o > 0; o >>= 1)
        sum += __shfl_xor_sync(0xffffffffu, sum, o);
    if (lane == 0) red[warp] = sum;
    __syncthreads();
    {
        float t = red[lane & 15];
#pragma unroll
        for (int o = 8; o > 0; o >>= 1)
            t += __shfl_xor_sync(0xffffffffu, t, o);
        sum = __shfl_sync(0xffffffffu, t, 0);
    }
    const float inv = 1.0f / sum;
    __syncthreads();

    unsigned short* ph = (unsigned short*)(Ph + (size_t)r * n);
    for (int i = tid; i < nv; i += 512) {
        float4 v = r4[i];
        __half h0 = __float2half_rn(v.x * inv);
        __half h1 = __float2half_rn(v.y * inv);
        __half h2 = __float2half_rn(v.z * inv);
        __half h3 = __float2half_rn(v.w * inv);
        int2 wh;
        wh.x = (int)((uint32_t)*(unsigned short*)&h0 |
                     ((uint32_t)*(unsigned short*)&h1 << 16));
        wh.y = (int)((uint32_t)*(unsigned short*)&h2 |
                     ((uint32_t)*(unsigned short*)&h3 << 16));
        __stcs((int2*)(ph + i * 4), wh);
    }
}

// ---------------------------------------------------------------------------
extern "C" void kernel_launch(void* const* d_in, const int* in_sizes, int n_in,
                              void* d_out, int out_size)
{
    const float* X  = (const float*)d_in[0];
    const float* Wq = (const float*)d_in[1];
    const float* Wk = (const float*)d_in[2];
    float* out = (float*)d_out;

    void* p;
#define SYM(name, var) cudaGetSymbolAddress(&p, name); auto* var = (decltype(&name[0]))p;
    SYM(g_S, S) SYM(g_Ph, Ph)
    SYM(g_Qh, Qh) SYM(g_Qm, Qm)
    SYM(g_Kh, Kh) SYM(g_Km, Km)
    SYM(g_Xh, Xh) SYM(g_Xm, Xm)
    SYM(g_Xth, Xth)
    SYM(g_Wqh, Wqh) SYM(g_Wqm, Wqm)
    SYM(g_Wkh, Wkh) SYM(g_Wkm, Wkm)
#undef SYM

    const int SMEM_M0 = 3 * 32768;   // 3 stages x 32KB (2 CTAs/SM)
    const int SMEM_M1 = 6 * 16384;   // 6 stages x 16KB (2 CTAs/SM)
    cudaFuncSetAttribute(gemm_mma<0, 1>, cudaFuncAttributeMaxDynamicSharedMemorySize, SMEM_M0);
    cudaFuncSetAttribute(gemm_mma<0, 0>, cudaFuncAttributeMaxDynamicSharedMemorySize, SMEM_M0);
    cudaFuncSetAttribute(gemm_mma<1, 0>, cudaFuncAttributeMaxDynamicSharedMemorySize, SMEM_M1);

    // side stream + events for the QK->softmax->PV row-chunk pipeline
    cudaStream_t s1;
    cudaStreamCreateWithFlags(&s1, cudaStreamNonBlocking);
    cudaEvent_t evq[NCH], evd;
    for (int c = 0; c < NCH; c++)
        cudaEventCreateWithFlags(&evq[c], cudaEventDisableTiming);
    cudaEventCreateWithFlags(&evd, cudaEventDisableTiming);

    // --- prep (main stream) ---
    prep_x<<<dim3(DIM / 32, SEQ / 32), 256>>>(X, Xh, Xm, Xth);
    transp_split2h_dual<<<dim3(DIM / 32, DIM / 32, 2), 256>>>(
        Wq, Wqh, Wqm, Wk, Wkh, Wkm, DIM, DIM);

    // --- projections Q and K in one launch (z selects weight set) ---
    {
        GemmArgs a{};
        a.A[0] = Xh;  a.A[1] = Xm;
        a.B[0] = Wqh; a.B[1] = Wqm;
        a.B2[0] = Wkh; a.B2[1] = Wkm;
        a.K = DIM; a.ldc = DIM; a.moff = 0; a.alpha = 1.0f;
        a.Oh = Qh; a.Om = Qm; a.Oh2 = Kh; a.Om2 = Km;
        gemm_mma<0, 1><<<dim3(DIM / 128, SEQ / 128, 2), 128, SMEM_M0>>>(a);
    }

    // --- pipelined: QK chunk c (main) ; softmax_c + PV_c (s1) ---
    for (int c = 0; c < NCH; c++) {
        {
            GemmArgs a{};
            a.A[0] = Qh; a.A[1] = Qm;
            a.B[0] = Kh; a.B[1] = Km;
            a.K = DIM; a.ldc = SEQ; a.moff = c * CHROWS; a.alpha = 0.03125f;
            a.C = S;
            gemm_mma<0, 0><<<dim3(SEQ / 128, CHROWS / 128, 1), 128, SMEM_M0>>>(a);
        }
        cudaEventRecord(evq[c], 0);
        cudaStreamWaitEvent(s1, evq[c], 0);
        softmax_h<<<CHROWS, 512, 0, s1>>>(S, Ph, SEQ, c * CHROWS);
        {
            GemmArgs a{};
            a.A[0] = Ph;
            a.B[0] = Xth;
            a.K = SEQ; a.ldc = DIM; a.moff = c * CHROWS; a.alpha = 1.0f;
            a.C = out;
            gemm_mma<1, 0><<<dim3(DIM / 128, CHROWS / 128, 1), 128, SMEM_M1, s1>>>(a);
        }
    }

    // join side stream back into the main stream
    cudaEventRecord(evd, s1);
    cudaStreamWaitEvent(0, evd, 0);

    for (int c = 0; c < NCH; c++) cudaEventDestroy(evq[c]);
    cudaEventDestroy(evd);
    cudaStreamDestroy(s1);
}

// round 16
// speedup vs baseline: 1.0701x; 1.0242x over previous
#include <cuda_runtime.h>
#include <cuda_bf16.h>
#include <cuda_fp16.h>
#include <cstdint>
#include <math.h>

#define SEQ 8192
#define DIM 1024

// ---------------------------------------------------------------------------
// Scratch (device globals — allocation-free)
// ---------------------------------------------------------------------------
__device__ __align__(256) float g_S[(size_t)SEQ * SEQ];     // 256MB logits
__device__ __align__(256) __half g_Ph[(size_t)SEQ * SEQ];   // 128MB probs (fp16)
__device__ __align__(256) __half g_Qh[SEQ * DIM], g_Qm[SEQ * DIM];
__device__ __align__(256) __half g_Kh[SEQ * DIM], g_Km[SEQ * DIM];
__device__ __align__(256) __half g_Xh[SEQ * DIM], g_Xm[SEQ * DIM];
__device__ __align__(256) __half g_Xth[DIM * SEQ];
__device__ __align__(256) __half g_Wqh[DIM * DIM], g_Wqm[DIM * DIM];
__device__ __align__(256) __half g_Wkh[DIM * DIM], g_Wkm[DIM * DIM];

// ---------------------------------------------------------------------------
// PTX helpers (baseline ISA only — valid on .target sm_103)
// ---------------------------------------------------------------------------
__device__ __forceinline__ uint32_t smem_u32(const void* p) {
    uint32_t a;
    asm("{ .reg .u64 t; cvta.to.shared.u64 t, %1; cvt.u32.u64 %0, t; }"
        : "=r"(a) : "l"(p));
    return a;
}

__device__ __forceinline__ void cp_async16(uint32_t saddr, const void* gaddr) {
    asm volatile("cp.async.cg.shared.global [%0], [%1], 16;"
                 :: "r"(saddr), "l"(gaddr));
}
#define CP_COMMIT() asm volatile("cp.async.commit_group;")
#define CP_WAIT(N)  asm volatile("cp.async.wait_group %0;" :: "n"(N))

__device__ __forceinline__ void ldsm4(uint32_t* r, uint32_t addr) {
    asm volatile("ldmatrix.sync.aligned.m8n8.x4.shared.b16 {%0,%1,%2,%3}, [%4];"
                 : "=r"(r[0]), "=r"(r[1]), "=r"(r[2]), "=r"(r[3])
                 : "r"(addr));
}

// fp16 inputs, fp32 accumulate
__device__ __forceinline__ void mma16816(float* d, const uint32_t* a,
                                         uint32_t b0, uint32_t b1) {
    asm volatile(
        "mma.sync.aligned.m16n8k16.row.col.f32.f16.f16.f32 "
        "{%0,%1,%2,%3}, {%4,%5,%6,%7}, {%8,%9}, {%0,%1,%2,%3};"
        : "+f"(d[0]), "+f"(d[1]), "+f"(d[2]), "+f"(d[3])
        : "r"(a[0]), "r"(a[1]), "r"(a[2]), "r"(a[3]), "r"(b0), "r"(b1));
}

// swizzled smem byte offset for (row, 16B-segment 0..3) in a 64B-pitch tile
__device__ __forceinline__ uint32_t swz64(int row, int seg) {
    return (uint32_t)(row * 64 + ((seg ^ ((row >> 1) & 3)) << 4));
}

// ---------------------------------------------------------------------------
// Multi-plane HMMA GEMM, all products accumulated into ONE output:
//   MODE 0:  D = alpha * (A0@B0^T + A0@B1^T + A1@B0^T)    (3-product split)
//   MODE 1:  D = alpha * (A0@B0^T)                        (plain GEMM)
// CTA: 128 threads (2x2 warps, warp tile 64x64), tile 128x128, BK=32.
// Stage = all planes of one K-chunk (32KB / 16KB); 3 / 6 stages = 96KB
// -> 2 CTAs per SM; fragments shared across products.
// EPI 0: C = alpha*D (fp32, streaming store). EPI 1: 2-way fp16 split of D.
// ---------------------------------------------------------------------------
struct GemmArgs {
    const void* A[2];
    const void* B[2];
    const void* B2[2];
    int K;        // reduction length (multiple of 32)
    int ldc;
    float alpha;
    float* C;
    __half *Oh, *Om, *Oh2, *Om2;
};

template <int MODE, int EPI>
__global__ __launch_bounds__(128, 2)
void gemm_mma(const GemmArgs args)
{
    constexpr int BM = 128, BN = 128, BK = 32;
    constexpr int NA = (MODE == 0) ? 2 : 1;
    constexpr int NB = (MODE == 0) ? 2 : 1;
    constexpr int STAGES = (MODE == 0) ? 3 : 6;
    constexpr int A_PL = BM * 64;                  // 8KB per A plane
    constexpr int B_PL = BN * 64;                  // 8KB per B plane
    constexpr int STAGE_B = NA * A_PL + NB * B_PL; // 32KB / 16KB
    extern __shared__ __align__(128) char smem[];
    const uint32_t sbase = smem_u32(smem);

    const int tid = threadIdx.x;
    const int wid = tid >> 5;
    const int lane = tid & 31;
    const int wm = wid & 1;          // 2 warps along M (64 rows each)
    const int wn = wid >> 1;         // 2 warps along N (64 cols each)
    const int bm = blockIdx.y * BM;
    const int bn = blockIdx.x * BN;
    const int K = args.K;
    const int nchunk = K / BK;
    const int z = blockIdx.z;
    const void* const* Bset = z ? args.B2 : args.B;

    // per-lane ldmatrix offsets: 2 k16-steps per BK=32 chunk
    const int sub = lane >> 3, r8 = lane & 7;
    uint32_t aoff[2][4], boff[2][4];
#pragma unroll
    for (int kk = 0; kk < 2; kk++) {
#pragma unroll
        for (int mi = 0; mi < 4; mi++) {
            int row = wm * 64 + mi * 16 + (sub & 1) * 8 + r8;
            int seg = 2 * kk + (sub >> 1);
            aoff[kk][mi] = swz64(row, seg);
        }
#pragma unroll
        for (int nj = 0; nj < 4; nj++) {
            int row = wn * 64 + nj * 16 + (sub >> 1) * 8 + r8;
            int seg = 2 * kk + (sub & 1);
            boff[kk][nj] = swz64(row, seg);
        }
    }

    // cp.async mapping: 32 rows x 4 segs per pass (128 threads)
    const int ld_row = tid >> 2;         // 0..31
    const int ld_seg = tid & 3;          // 0..3
    const size_t g_off0 = (size_t)ld_row * K + ld_seg * 8;

    float acc[4][8][4];
#pragma unroll
    for (int mi = 0; mi < 4; mi++)
#pragma unroll
        for (int ni = 0; ni < 8; ni++)
#pragma unroll
            for (int v = 0; v < 4; v++) acc[mi][ni][v] = 0.0f;

    auto issue_tile = [&](int c, int s) {
        const uint32_t sb = sbase + s * STAGE_B;
        const size_t rstep = (size_t)32 * K;
#pragma unroll
        for (int pl = 0; pl < NA; pl++) {
            const unsigned short* Ap =
                (const unsigned short*)args.A[pl] + (size_t)bm * K + c * BK;
            const uint32_t abase = sb + pl * A_PL;
#pragma unroll
            for (int r = 0; r < 4; r++)
                cp_async16(abase + swz64(ld_row + r * 32, ld_seg),
                           Ap + g_off0 + r * rstep);
        }
#pragma unroll
        for (int pl = 0; pl < NB; pl++) {
            const unsigned short* Bp =
                (const unsigned short*)Bset[pl] + (size_t)bn * K + c * BK;
            const uint32_t bbase = sb + NA * A_PL + pl * B_PL;
#pragma unroll
            for (int r = 0; r < 4; r++)
                cp_async16(bbase + swz64(ld_row + r * 32, ld_seg),
                           Bp + g_off0 + r * rstep);
        }
    };

    // prologue: stages 0..STAGES-2 in flight
#pragma unroll
    for (int j = 0; j < STAGES - 1; j++) {
        issue_tile(j, j);
        CP_COMMIT();
    }
    CP_WAIT(STAGES - 2);
    __syncthreads();

    for (int i = 0; i < nchunk; i++) {
        // fill slot (i+STAGES-1)%STAGES — freed by the barrier ending iter i-1
        if (i + STAGES - 1 < nchunk) {
            issue_tile(i + STAGES - 1, (i + STAGES - 1) % STAGES);
            CP_COMMIT();
        }

        const uint32_t sb = sbase + (i % STAGES) * STAGE_B;
        const uint32_t a0 = sb, a1 = sb + A_PL;
        const uint32_t b0 = sb + NA * A_PL, b1 = b0 + B_PL;
#pragma unroll
        for (int kk = 0; kk < 2; kk++) {
            uint32_t bh[4][4];
#pragma unroll
            for (int nj = 0; nj < 4; nj++) ldsm4(bh[nj], b0 + boff[kk][nj]);
            uint32_t bm_[4][4];
            if (MODE == 0) {
#pragma unroll
                for (int nj = 0; nj < 4; nj++) ldsm4(bm_[nj], b1 + boff[kk][nj]);
            }
#pragma unroll
            for (int mi = 0; mi < 4; mi++) {
                uint32_t ah[4];
                ldsm4(ah, a0 + aoff[kk][mi]);
#pragma unroll
                for (int ni = 0; ni < 8; ni++) {
                    const int nj = ni >> 1, o = (ni & 1) * 2;
                    mma16816(acc[mi][ni], ah, bh[nj][o], bh[nj][o + 1]);
                }
                if (MODE == 0) {
                    uint32_t am[4];
                    ldsm4(am, a1 + aoff[kk][mi]);
#pragma unroll
                    for (int ni = 0; ni < 8; ni++) {
                        const int nj = ni >> 1, o = (ni & 1) * 2;
                        mma16816(acc[mi][ni], ah, bm_[nj][o], bm_[nj][o + 1]);
                    }
#pragma unroll
                    for (int ni = 0; ni < 8; ni++) {
                        const int nj = ni >> 1, o = (ni & 1) * 2;
                        mma16816(acc[mi][ni], am, bh[nj][o], bh[nj][o + 1]);
                    }
                }
            }
        }
        CP_WAIT(STAGES - 2);   // next tile resident
        __syncthreads();       // everyone done reading this slot
    }

    // ---- epilogue from registers ----
    const int ldc = args.ldc;
    __half* Ohp = z ? args.Oh2 : args.Oh;
    __half* Omp = z ? args.Om2 : args.Om;
#pragma unroll
    for (int mi = 0; mi < 4; mi++) {
#pragma unroll
        for (int ni = 0; ni < 8; ni++) {
            const int r0 = bm + wm * 64 + mi * 16 + (lane >> 2);
            const int c0 = bn + wn * 64 + ni * 8 + (lane & 3) * 2;
#pragma unroll
            for (int h = 0; h < 2; h++) {
                const size_t o = (size_t)(r0 + h * 8) * ldc + c0;
                const float v0 = acc[mi][ni][2 * h + 0];
                const float v1 = acc[mi][ni][2 * h + 1];
                if (EPI == 0) {
                    float2 w;
                    w.x = args.alpha * v0;
                    w.y = args.alpha * v1;
                    __stcs((float2*)(args.C + o), w);
                } else {
                    __half h0 = __float2half_rn(v0);
                    __half h1 = __float2half_rn(v1);
                    __half m0 = __float2half_rn(v0 - __half2float(h0));
                    __half m1 = __float2half_rn(v1 - __half2float(h1));
                    uint32_t ph = (uint32_t)*(unsigned short*)&h0 |
                                  ((uint32_t)*(unsigned short*)&h1 << 16);
                    uint32_t pm = (uint32_t)*(unsigned short*)&m0 |
                                  ((uint32_t)*(unsigned short*)&m1 << 16);
                    *(uint32_t*)((unsigned short*)Ohp + o) = ph;
                    *(uint32_t*)((unsigned short*)Omp + o) = pm;
                }
            }
        }
    }
}

// ---------------------------------------------------------------------------
// prep_x: one read of X -> Xh, Xm (row-major fp16 split) + Xth (fp16 transpose)
// ---------------------------------------------------------------------------
__global__ __launch_bounds__(256)
void prep_x(const float* __restrict__ X, __half* __restrict__ Xh,
            __half* __restrict__ Xm, __half* __restrict__ Xth)
{
    __shared__ float t[32][33];
    const int bc = blockIdx.x * 32, br = blockIdx.y * 32;
    const int tx = threadIdx.x & 31, ty = threadIdx.x >> 5;
#pragma unroll
    for (int j = 0; j < 32; j += 8) {
        size_t idx = (size_t)(br + ty + j) * DIM + bc + tx;
        float v = X[idx];
        t[ty + j][tx] = v;
        __half h = __float2half_rn(v);
        Xh[idx] = h;
        Xm[idx] = __float2half_rn(v - __half2float(h));
    }
    __syncthreads();
#pragma unroll
    for (int j = 0; j < 32; j += 8) {
        int oc = bc + ty + j;
        Xth[(size_t)oc * SEQ + br + tx] = __float2half_rn(t[tx][ty + j]);
    }
}

// ---------------------------------------------------------------------------
// transpose + 2-way fp16 split: in[R][C] fp32 -> oh/om [C][R] fp16
// blockIdx.z selects (input, output) pair — merged Wq/Wk transpose.
// ---------------------------------------------------------------------------
__global__ __launch_bounds__(256)
void transp_split2h_dual(const float* __restrict__ in0, __half* oh0, __half* om0,
                         const float* __restrict__ in1, __half* oh1, __half* om1,
                         int R, int C)
{
    const float* in = blockIdx.z ? in1 : in0;
    __half* oh = blockIdx.z ? oh1 : oh0;
    __half* om = blockIdx.z ? om1 : om0;
    __shared__ float t[32][33];
    const int bc = blockIdx.x * 32, br = blockIdx.y * 32;
    const int tx = threadIdx.x & 31, ty = threadIdx.x >> 5;
#pragma unroll
    for (int j = 0; j < 32; j += 8)
        t[ty + j][tx] = in[(size_t)(br + ty + j) * C + bc + tx];
    __syncthreads();
#pragma unroll
    for (int j = 0; j < 32; j += 8) {
        int oc = bc + ty + j;
        float v = t[tx][ty + j];
        __half h = __float2half_rn(v);
        size_t o = (size_t)oc * R + br + tx;
        oh[o] = h;
        om[o] = __float2half_rn(v - __half2float(h));
    }
}

// ---------------------------------------------------------------------------
// softmax over rows of S, emitting fp16 P. 512 threads, float4 streaming
// loads, __expf, shuffle+smem reductions, streaming vectorized stores.
// ---------------------------------------------------------------------------
__global__ __launch_bounds__(512)
void softmax_h(const float* __restrict__ S, __half* __restrict__ Ph, int n)
{
    __shared__ float row[SEQ];
    __shared__ float red[16];
    const int tid = threadIdx.x;
    const int lane = tid & 31;
    const int warp = tid >> 5;
    const int nv = n / 4;
    const float4* s4 = (const float4*)(S + (size_t)blockIdx.x * n);
    float4* r4 = (float4*)row;

    float m = -3.4e38f;
    for (int i = tid; i < nv; i += 512) {
        float4 v = __ldcs(s4 + i);
        r4[i] = v;
        m = fmaxf(fmaxf(m, v.x), fmaxf(v.y, fmaxf(v.z, v.w)));
    }
#pragma unroll
    for (int o = 16; o > 0; o >>= 1)
        m = fmaxf(m, __shfl_xor_sync(0xffffffffu, m, o));
    if (lane == 0) red[warp] = m;
    __syncthreads();
    {
        float t = red[lane & 15];
#pragma unroll
        for (int o = 8; o > 0; o >>= 1)
            t = fmaxf(t, __shfl_xor_sync(0xffffffffu, t, o));
        m = __shfl_sync(0xffffffffu, t, 0);
    }
    __syncthreads();

    float sum = 0.0f;
    for (int i = tid; i < nv; i += 512) {
        float4 v = r4[i];
        v.x = __expf(v.x - m);
        v.y = __expf(v.y - m);
        v.z = __expf(v.z - m);
        v.w = __expf(v.w - m);
        r4[i] = v;
        sum += v.x + v.y + v.z + v.w;
    }
#pragma unroll
    for (int o = 16; o > 0; o >>= 1)
        sum += __shfl_xor_sync(0xffffffffu, sum, o);
    if (lane == 0) red[warp] = sum;
    __syncthreads();
    {
        float t = red[lane & 15];
#pragma unroll
        for (int o = 8; o > 0; o >>= 1)
            t += __shfl_xor_sync(0xffffffffu, t, o);
        sum = __shfl_sync(0xffffffffu, t, 0);
    }
    const float inv = 1.0f / sum;
    __syncthreads();

    unsigned short* ph = (unsigned short*)(Ph + (size_t)blockIdx.x * n);
    for (int i = tid; i < nv; i += 512) {
        float4 v = r4[i];
        __half h0 = __float2half_rn(v.x * inv);
        __half h1 = __float2half_rn(v.y * inv);
        __half h2 = __float2half_rn(v.z * inv);
        __half h3 = __float2half_rn(v.w * inv);
        int2 wh;
        wh.x = (int)((uint32_t)*(unsigned short*)&h0 |
                     ((uint32_t)*(unsigned short*)&h1 << 16));
        wh.y = (int)((uint32_t)*(unsigned short*)&h2 |
                     ((uint32_t)*(unsigned short*)&h3 << 16));
        __stcs((int2*)(ph + i * 4), wh);
    }
}

// ---------------------------------------------------------------------------
extern "C" void kernel_launch(void* const* d_in, const int* in_sizes, int n_in,
                              void* d_out, int out_size)
{
    const float* X  = (const float*)d_in[0];
    const float* Wq = (const float*)d_in[1];
    const float* Wk = (const float*)d_in[2];
    float* out = (float*)d_out;

    void* p;
#define SYM(name, var) cudaGetSymbolAddress(&p, name); auto* var = (decltype(&name[0]))p;
    SYM(g_S, S) SYM(g_Ph, Ph)
    SYM(g_Qh, Qh) SYM(g_Qm, Qm)
    SYM(g_Kh, Kh) SYM(g_Km, Km)
    SYM(g_Xh, Xh) SYM(g_Xm, Xm)
    SYM(g_Xth, Xth)
    SYM(g_Wqh, Wqh) SYM(g_Wqm, Wqm)
    SYM(g_Wkh, Wkh) SYM(g_Wkm, Wkm)
#undef SYM

    const int SMEM_M0 = 3 * 32768;   // 3 stages x 32KB (2 CTAs/SM)
    const int SMEM_M1 = 6 * 16384;   // 6 stages x 16KB (2 CTAs/SM)
    cudaFuncSetAttribute(gemm_mma<0, 1>, cudaFuncAttributeMaxDynamicSharedMemorySize, SMEM_M0);
    cudaFuncSetAttribute(gemm_mma<0, 0>, cudaFuncAttributeMaxDynamicSharedMemorySize, SMEM_M0);
    cudaFuncSetAttribute(gemm_mma<1, 0>, cudaFuncAttributeMaxDynamicSharedMemorySize, SMEM_M1);

    // --- prep: one-read X split+transpose, merged Wq/Wk transpose ---
    prep_x<<<dim3(DIM / 32, SEQ / 32), 256>>>(X, Xh, Xm, Xth);
    transp_split2h_dual<<<dim3(DIM / 32, DIM / 32, 2), 256>>>(
        Wq, Wqh, Wqm, Wk, Wkh, Wkm, DIM, DIM);

    // --- projections Q and K in one launch (z selects weight set) ---
    {
        GemmArgs a{};
        a.A[0] = Xh;  a.A[1] = Xm;
        a.B[0] = Wqh; a.B[1] = Wqm;
        a.B2[0] = Wkh; a.B2[1] = Wkm;
        a.K = DIM; a.ldc = DIM; a.alpha = 1.0f;
        a.Oh = Qh; a.Om = Qm; a.Oh2 = Kh; a.Om2 = Km;
        gemm_mma<0, 1><<<dim3(DIM / 128, SEQ / 128, 2), 128, SMEM_M0>>>(a);
    }
    // --- S = (Q @ K^T) / 32 : products {hh, hm, mh} ---
    {
        GemmArgs a{};
        a.A[0] = Qh; a.A[1] = Qm;
        a.B[0] = Kh; a.B[1] = Km;
        a.K = DIM; a.ldc = SEQ; a.alpha = 0.03125f;
        a.C = S;
        gemm_mma<0, 0><<<dim3(SEQ / 128, SEQ / 128, 1), 128, SMEM_M0>>>(a);
    }
    // --- softmax -> fp16 P ---
    softmax_h<<<SEQ, 512>>>(S, Ph, SEQ);
    // --- out = Ph @ Xth^T : single fp16 product ---
    {
        GemmArgs a{};
        a.A[0] = Ph;
        a.B[0] = Xth;
        a.K = SEQ; a.ldc = DIM; a.alpha = 1.0f;
        a.C = out;
        gemm_mma<1, 0><<<dim3(DIM / 128, SEQ / 128, 1), 128, SMEM_M1>>>(a);
    }
}

// round 17
// speedup vs baseline: 1.0722x; 1.0020x over previous
#include <cuda_runtime.h>
#include <cuda_bf16.h>
#include <cuda_fp16.h>
#include <cstdint>
#include <math.h>

#define SEQ 8192
#define DIM 1024

// ---------------------------------------------------------------------------
// Scratch (device globals — allocation-free)
// ---------------------------------------------------------------------------
__device__ __align__(256) float g_S[(size_t)SEQ * SEQ];     // 256MB logits
__device__ __align__(256) __half g_Ph[(size_t)SEQ * SEQ];   // 128MB probs (fp16)
__device__ __align__(256) __half g_Qh[SEQ * DIM], g_Qm[SEQ * DIM];
__device__ __align__(256) __half g_Kh[SEQ * DIM], g_Km[SEQ * DIM];
__device__ __align__(256) __half g_Xh[SEQ * DIM], g_Xm[SEQ * DIM];
__device__ __align__(256) __half g_Xth[DIM * SEQ];
__device__ __align__(256) __half g_Wqh[DIM * DIM], g_Wqm[DIM * DIM];
__device__ __align__(256) __half g_Wkh[DIM * DIM], g_Wkm[DIM * DIM];

// ---------------------------------------------------------------------------
// PTX helpers (baseline ISA only — valid on .target sm_103)
// ---------------------------------------------------------------------------
__device__ __forceinline__ uint32_t smem_u32(const void* p) {
    uint32_t a;
    asm("{ .reg .u64 t; cvta.to.shared.u64 t, %1; cvt.u32.u64 %0, t; }"
        : "=r"(a) : "l"(p));
    return a;
}

__device__ __forceinline__ void cp_async16(uint32_t saddr, const void* gaddr) {
    asm volatile("cp.async.cg.shared.global [%0], [%1], 16;"
                 :: "r"(saddr), "l"(gaddr));
}
#define CP_COMMIT() asm volatile("cp.async.commit_group;")
#define CP_WAIT(N)  asm volatile("cp.async.wait_group %0;" :: "n"(N))

__device__ __forceinline__ void ldsm4(uint32_t* r, uint32_t addr) {
    asm volatile("ldmatrix.sync.aligned.m8n8.x4.shared.b16 {%0,%1,%2,%3}, [%4];"
                 : "=r"(r[0]), "=r"(r[1]), "=r"(r[2]), "=r"(r[3])
                 : "r"(addr));
}

// fp16 inputs, fp32 accumulate
__device__ __forceinline__ void mma16816(float* d, const uint32_t* a,
                                         uint32_t b0, uint32_t b1) {
    asm volatile(
        "mma.sync.aligned.m16n8k16.row.col.f32.f16.f16.f32 "
        "{%0,%1,%2,%3}, {%4,%5,%6,%7}, {%8,%9}, {%0,%1,%2,%3};"
        : "+f"(d[0]), "+f"(d[1]), "+f"(d[2]), "+f"(d[3])
        : "r"(a[0]), "r"(a[1]), "r"(a[2]), "r"(a[3]), "r"(b0), "r"(b1));
}

// swizzled smem byte offset for (row, 16B-seg) — PITCH = 64 or 128 bytes
template <int PITCH>
__device__ __forceinline__ uint32_t swz(int row, int seg) {
    if (PITCH == 64)
        return (uint32_t)(row * 64 + ((seg ^ ((row >> 1) & 3)) << 4));
    else
        return (uint32_t)(row * 128 + ((seg ^ (row & 7)) << 4));
}

// ---------------------------------------------------------------------------
// Multi-plane HMMA GEMM, all products accumulated into ONE output:
//   MODE 0:  D = alpha*(A0@B0^T + A0@B1^T + A1@B0^T)   BK=32 (3-product split)
//   MODE 1:  D = alpha*(A0@B0^T)                       BK=64 (plain GEMM)
// CTA: 128 threads (2x2 warps, warp tile 64x64), tile 128x128.
// Stage = all planes of one K-chunk (32KB either mode); 3 stages = 96KB
// -> 2 CTAs per SM; fragments shared across products (MODE 0).
// EPI 0: C = alpha*D (fp32, streaming store). EPI 1: 2-way fp16 split of D.
// ---------------------------------------------------------------------------
struct GemmArgs {
    const void* A[2];
    const void* B[2];
    const void* B2[2];
    int K;        // reduction length (multiple of BK)
    int ldc;
    float alpha;
    float* C;
    __half *Oh, *Om, *Oh2, *Om2;
};

template <int MODE, int EPI>
__global__ __launch_bounds__(128, 2)
void gemm_mma(const GemmArgs args)
{
    constexpr int BM = 128, BN = 128;
    constexpr int BK = (MODE == 0) ? 32 : 64;
    constexpr int PITCH = BK * 2;                  // bytes per row
    constexpr int KKN = BK / 16;                   // k16 steps per chunk
    constexpr int NA = (MODE == 0) ? 2 : 1;
    constexpr int NB = (MODE == 0) ? 2 : 1;
    constexpr int STAGES = 3;
    constexpr int A_PL = BM * PITCH;               // 8KB / 16KB
    constexpr int B_PL = BN * PITCH;
    constexpr int STAGE_B = NA * A_PL + NB * B_PL; // 32KB both modes
    extern __shared__ __align__(128) char smem[];
    const uint32_t sbase = smem_u32(smem);

    const int tid = threadIdx.x;
    const int wid = tid >> 5;
    const int lane = tid & 31;
    const int wm = wid & 1;          // 2 warps along M (64 rows each)
    const int wn = wid >> 1;         // 2 warps along N (64 cols each)
    const int bm = blockIdx.y * BM;
    const int bn = blockIdx.x * BN;
    const int K = args.K;
    const int nchunk = K / BK;
    const int z = blockIdx.z;
    const void* const* Bset = z ? args.B2 : args.B;

    // per-lane ldmatrix offsets: KKN k16-steps per chunk
    const int sub = lane >> 3, r8 = lane & 7;
    uint32_t aoff[KKN][4], boff[KKN][4];
#pragma unroll
    for (int kk = 0; kk < KKN; kk++) {
#pragma unroll
        for (int mi = 0; mi < 4; mi++) {
            int row = wm * 64 + mi * 16 + (sub & 1) * 8 + r8;
            int seg = 2 * kk + (sub >> 1);
            aoff[kk][mi] = swz<PITCH>(row, seg);
        }
#pragma unroll
        for (int nj = 0; nj < 4; nj++) {
            int row = wn * 64 + nj * 16 + (sub >> 1) * 8 + r8;
            int seg = 2 * kk + (sub & 1);
            boff[kk][nj] = swz<PITCH>(row, seg);
        }
    }

    // cp.async mapping (128 threads):
    //   MODE 0: 32 rows x 4 segs per pass, 4 passes per plane
    //   MODE 1: 16 rows x 8 segs per pass, 8 passes per plane
    constexpr int LD_SEGS = PITCH / 16;            // 4 / 8
    constexpr int LD_ROWS = 128 / LD_SEGS;         // 32 / 16
    constexpr int LD_PASS = BM / LD_ROWS;          // 4 / 8
    const int ld_row = tid / LD_SEGS;
    const int ld_seg = tid % LD_SEGS;
    const size_t g_off0 = (size_t)ld_row * K + ld_seg * 8;

    float acc[4][8][4];
#pragma unroll
    for (int mi = 0; mi < 4; mi++)
#pragma unroll
        for (int ni = 0; ni < 8; ni++)
#pragma unroll
            for (int v = 0; v < 4; v++) acc[mi][ni][v] = 0.0f;

    auto issue_tile = [&](int c, int s) {
        const uint32_t sb = sbase + s * STAGE_B;
        const size_t rstep = (size_t)LD_ROWS * K;
#pragma unroll
        for (int pl = 0; pl < NA; pl++) {
            const unsigned short* Ap =
                (const unsigned short*)args.A[pl] + (size_t)bm * K + c * BK;
            const uint32_t abase = sb + pl * A_PL;
#pragma unroll
            for (int r = 0; r < LD_PASS; r++)
                cp_async16(abase + swz<PITCH>(ld_row + r * LD_ROWS, ld_seg),
                           Ap + g_off0 + r * rstep);
        }
#pragma unroll
        for (int pl = 0; pl < NB; pl++) {
            const unsigned short* Bp =
                (const unsigned short*)Bset[pl] + (size_t)bn * K + c * BK;
            const uint32_t bbase = sb + NA * A_PL + pl * B_PL;
#pragma unroll
            for (int r = 0; r < LD_PASS; r++)
                cp_async16(bbase + swz<PITCH>(ld_row + r * LD_ROWS, ld_seg),
                           Bp + g_off0 + r * rstep);
        }
    };

    // prologue: stages 0..STAGES-2 in flight
#pragma unroll
    for (int j = 0; j < STAGES - 1; j++) {
        issue_tile(j, j);
        CP_COMMIT();
    }
    CP_WAIT(STAGES - 2);
    __syncthreads();

    for (int i = 0; i < nchunk; i++) {
        // fill slot (i+STAGES-1)%STAGES — freed by the barrier ending iter i-1
        if (i + STAGES - 1 < nchunk) {
            issue_tile(i + STAGES - 1, (i + STAGES - 1) % STAGES);
            CP_COMMIT();
        }

        const uint32_t sb = sbase + (i % STAGES) * STAGE_B;
        const uint32_t a0 = sb, a1 = sb + A_PL;
        const uint32_t b0 = sb + NA * A_PL, b1 = b0 + B_PL;
#pragma unroll
        for (int kk = 0; kk < KKN; kk++) {
            uint32_t bh[4][4];
#pragma unroll
            for (int nj = 0; nj < 4; nj++) ldsm4(bh[nj], b0 + boff[kk][nj]);
            uint32_t bm_[4][4];
            if (MODE == 0) {
#pragma unroll
                for (int nj = 0; nj < 4; nj++) ldsm4(bm_[nj], b1 + boff[kk][nj]);
            }
#pragma unroll
            for (int mi = 0; mi < 4; mi++) {
                uint32_t ah[4];
                ldsm4(ah, a0 + aoff[kk][mi]);
#pragma unroll
                for (int ni = 0; ni < 8; ni++) {
                    const int nj = ni >> 1, o = (ni & 1) * 2;
                    mma16816(acc[mi][ni], ah, bh[nj][o], bh[nj][o + 1]);
                }
                if (MODE == 0) {
                    uint32_t am[4];
                    ldsm4(am, a1 + aoff[kk][mi]);
#pragma unroll
                    for (int ni = 0; ni < 8; ni++) {
                        const int nj = ni >> 1, o = (ni & 1) * 2;
                        mma16816(acc[mi][ni], ah, bm_[nj][o], bm_[nj][o + 1]);
                    }
#pragma unroll
                    for (int ni = 0; ni < 8; ni++) {
                        const int nj = ni >> 1, o = (ni & 1) * 2;
                        mma16816(acc[mi][ni], am, bh[nj][o], bh[nj][o + 1]);
                    }
                }
            }
        }
        CP_WAIT(STAGES - 2);   // next tile resident
        __syncthreads();       // everyone done reading this slot
    }

    // ---- epilogue from registers ----
    const int ldc = args.ldc;
    __half* Ohp = z ? args.Oh2 : args.Oh;
    __half* Omp = z ? args.Om2 : args.Om;
#pragma unroll
    for (int mi = 0; mi < 4; mi++) {
#pragma unroll
        for (int ni = 0; ni < 8; ni++) {
            const int r0 = bm + wm * 64 + mi * 16 + (lane >> 2);
            const int c0 = bn + wn * 64 + ni * 8 + (lane & 3) * 2;
#pragma unroll
            for (int h = 0; h < 2; h++) {
                const size_t o = (size_t)(r0 + h * 8) * ldc + c0;
                const float v0 = acc[mi][ni][2 * h + 0];
                const float v1 = acc[mi][ni][2 * h + 1];
                if (EPI == 0) {
                    float2 w;
                    w.x = args.alpha * v0;
                    w.y = args.alpha * v1;
                    __stcs((float2*)(args.C + o), w);
                } else {
                    __half h0 = __float2half_rn(v0);
                    __half h1 = __float2half_rn(v1);
                    __half m0 = __float2half_rn(v0 - __half2float(h0));
                    __half m1 = __float2half_rn(v1 - __half2float(h1));
                    uint32_t ph = (uint32_t)*(unsigned short*)&h0 |
                                  ((uint32_t)*(unsigned short*)&h1 << 16);
                    uint32_t pm = (uint32_t)*(unsigned short*)&m0 |
                                  ((uint32_t)*(unsigned short*)&m1 << 16);
                    *(uint32_t*)((unsigned short*)Ohp + o) = ph;
                    *(uint32_t*)((unsigned short*)Omp + o) = pm;
                }
            }
        }
    }
}

// ---------------------------------------------------------------------------
// prep_x: one read of X -> Xh, Xm (row-major fp16 split) + Xth (fp16 transpose)
// ---------------------------------------------------------------------------
__global__ __launch_bounds__(256)
void prep_x(const float* __restrict__ X, __half* __restrict__ Xh,
            __half* __restrict__ Xm, __half* __restrict__ Xth)
{
    __shared__ float t[32][33];
    const int bc = blockIdx.x * 32, br = blockIdx.y * 32;
    const int tx = threadIdx.x & 31, ty = threadIdx.x >> 5;
#pragma unroll
    for (int j = 0; j < 32; j += 8) {
        size_t idx = (size_t)(br + ty + j) * DIM + bc + tx;
        float v = X[idx];
        t[ty + j][tx] = v;
        __half h = __float2half_rn(v);
        Xh[idx] = h;
        Xm[idx] = __float2half_rn(v - __half2float(h));
    }
    __syncthreads();
#pragma unroll
    for (int j = 0; j < 32; j += 8) {
        int oc = bc + ty + j;
        Xth[(size_t)oc * SEQ + br + tx] = __float2half_rn(t[tx][ty + j]);
    }
}

// ---------------------------------------------------------------------------
// transpose + 2-way fp16 split: in[R][C] fp32 -> oh/om [C][R] fp16
// blockIdx.z selects (input, output) pair — merged Wq/Wk transpose.
// ---------------------------------------------------------------------------
__global__ __launch_bounds__(256)
void transp_split2h_dual(const float* __restrict__ in0, __half* oh0, __half* om0,
                         const float* __restrict__ in1, __half* oh1, __half* om1,
                         int R, int C)
{
    const float* in = blockIdx.z ? in1 : in0;
    __half* oh = blockIdx.z ? oh1 : oh0;
    __half* om = blockIdx.z ? om1 : om0;
    __shared__ float t[32][33];
    const int bc = blockIdx.x * 32, br = blockIdx.y * 32;
    const int tx = threadIdx.x & 31, ty = threadIdx.x >> 5;
#pragma unroll
    for (int j = 0; j < 32; j += 8)
        t[ty + j][tx] = in[(size_t)(br + ty + j) * C + bc + tx];
    __syncthreads();
#pragma unroll
    for (int j = 0; j < 32; j += 8) {
        int oc = bc + ty + j;
        float v = t[tx][ty + j];
        __half h = __float2half_rn(v);
        size_t o = (size_t)oc * R + br + tx;
        oh[o] = h;
        om[o] = __float2half_rn(v - __half2float(h));
    }
}

// ---------------------------------------------------------------------------
// softmax over rows of S, emitting fp16 P. 512 threads, float4 streaming
// loads, __expf, shuffle+smem reductions, streaming vectorized stores.
// ---------------------------------------------------------------------------
__global__ __launch_bounds__(512)
void softmax_h(const float* __restrict__ S, __half* __restrict__ Ph, int n)
{
    __shared__ float row[SEQ];
    __shared__ float red[16];
    const int tid = threadIdx.x;
    const int lane = tid & 31;
    const int warp = tid >> 5;
    const int nv = n / 4;
    const float4* s4 = (const float4*)(S + (size_t)blockIdx.x * n);
    float4* r4 = (float4*)row;

    float m = -3.4e38f;
    for (int i = tid; i < nv; i += 512) {
        float4 v = __ldcs(s4 + i);
        r4[i] = v;
        m = fmaxf(fmaxf(m, v.x), fmaxf(v.y, fmaxf(v.z, v.w)));
    }
#pragma unroll
    for (int o = 16; o > 0; o >>= 1)
        m = fmaxf(m, __shfl_xor_sync(0xffffffffu, m, o));
    if (lane == 0) red[warp] = m;
    __syncthreads();
    {
        float t = red[lane & 15];
#pragma unroll
        for (int o = 8; o > 0; o >>= 1)
            t = fmaxf(t, __shfl_xor_sync(0xffffffffu, t, o));
        m = __shfl_sync(0xffffffffu, t, 0);
    }
    __syncthreads();

    float sum = 0.0f;
    for (int i = tid; i < nv; i += 512) {
        float4 v = r4[i];
        v.x = __expf(v.x - m);
        v.y = __expf(v.y - m);
        v.z = __expf(v.z - m);
        v.w = __expf(v.w - m);
        r4[i] = v;
        sum += v.x + v.y + v.z + v.w;
    }
#pragma unroll
    for (int o = 16; o > 0; o >>= 1)
        sum += __shfl_xor_sync(0xffffffffu, sum, o);
    if (lane == 0) red[warp] = sum;
    __syncthreads();
    {
        float t = red[lane & 15];
#pragma unroll
        for (int o = 8; o > 0; o >>= 1)
            t += __shfl_xor_sync(0xffffffffu, t, o);
        sum = __shfl_sync(0xffffffffu, t, 0);
    }
    const float inv = 1.0f / sum;
    __syncthreads();

    unsigned short* ph = (unsigned short*)(Ph + (size_t)blockIdx.x * n);
    for (int i = tid; i < nv; i += 512) {
        float4 v = r4[i];
        __half h0 = __float2half_rn(v.x * inv);
        __half h1 = __float2half_rn(v.y * inv);
        __half h2 = __float2half_rn(v.z * inv);
        __half h3 = __float2half_rn(v.w * inv);
        int2 wh;
        wh.x = (int)((uint32_t)*(unsigned short*)&h0 |
                     ((uint32_t)*(unsigned short*)&h1 << 16));
        wh.y = (int)((uint32_t)*(unsigned short*)&h2 |
                     ((uint32_t)*(unsigned short*)&h3 << 16));
        __stcs((int2*)(ph + i * 4), wh);
    }
}

// ---------------------------------------------------------------------------
extern "C" void kernel_launch(void* const* d_in, const int* in_sizes, int n_in,
                              void* d_out, int out_size)
{
    const float* X  = (const float*)d_in[0];
    const float* Wq = (const float*)d_in[1];
    const float* Wk = (const float*)d_in[2];
    float* out = (float*)d_out;

    void* p;
#define SYM(name, var) cudaGetSymbolAddress(&p, name); auto* var = (decltype(&name[0]))p;
    SYM(g_S, S) SYM(g_Ph, Ph)
    SYM(g_Qh, Qh) SYM(g_Qm, Qm)
    SYM(g_Kh, Kh) SYM(g_Km, Km)
    SYM(g_Xh, Xh) SYM(g_Xm, Xm)
    SYM(g_Xth, Xth)
    SYM(g_Wqh, Wqh) SYM(g_Wqm, Wqm)
    SYM(g_Wkh, Wkh) SYM(g_Wkm, Wkm)
#undef SYM

    const int SMEM_GEMM = 3 * 32768;   // 3 stages x 32KB (2 CTAs/SM, both modes)
    cudaFuncSetAttribute(gemm_mma<0, 1>, cudaFuncAttributeMaxDynamicSharedMemorySize, SMEM_GEMM);
    cudaFuncSetAttribute(gemm_mma<0, 0>, cudaFuncAttributeMaxDynamicSharedMemorySize, SMEM_GEMM);
    cudaFuncSetAttribute(gemm_mma<1, 0>, cudaFuncAttributeMaxDynamicSharedMemorySize, SMEM_GEMM);

    // --- prep: one-read X split+transpose, merged Wq/Wk transpose ---
    prep_x<<<dim3(DIM / 32, SEQ / 32), 256>>>(X, Xh, Xm, Xth);
    transp_split2h_dual<<<dim3(DIM / 32, DIM / 32, 2), 256>>>(
        Wq, Wqh, Wqm, Wk, Wkh, Wkm, DIM, DIM);

    // --- projections Q and K in one launch (z selects weight set) ---
    {
        GemmArgs a{};
        a.A[0] = Xh;  a.A[1] = Xm;
        a.B[0] = Wqh; a.B[1] = Wqm;
        a.B2[0] = Wkh; a.B2[1] = Wkm;
        a.K = DIM; a.ldc = DIM; a.alpha = 1.0f;
        a.Oh = Qh; a.Om = Qm; a.Oh2 = Kh; a.Om2 = Km;
        gemm_mma<0, 1><<<dim3(DIM / 128, SEQ / 128, 2), 128, SMEM_GEMM>>>(a);
    }
    // --- S = (Q @ K^T) / 32 : products {hh, hm, mh} ---
    {
        GemmArgs a{};
        a.A[0] = Qh; a.A[1] = Qm;
        a.B[0] = Kh; a.B[1] = Km;
        a.K = DIM; a.ldc = SEQ; a.alpha = 0.03125f;
        a.C = S;
        gemm_mma<0, 0><<<dim3(SEQ / 128, SEQ / 128, 1), 128, SMEM_GEMM>>>(a);
    }
    // --- softmax -> fp16 P ---
    softmax_h<<<SEQ, 512>>>(S, Ph, SEQ);
    // --- out = Ph @ Xth^T : single fp16 product, BK=64 ---
    {
        GemmArgs a{};
        a.A[0] = Ph;
        a.B[0] = Xth;
        a.K = SEQ; a.ldc = DIM; a.alpha = 1.0f;
        a.C = out;
        gemm_mma<1, 0><<<dim3(DIM / 128, SEQ / 128, 1), 128, SMEM_GEMM>>>(a);
    }
}